// round 15
// baseline (speedup 1.0000x reference)
#include <cuda_runtime.h>
#include <cstdint>

// Problem constants (match reference)
#define S_NUM 2048
#define K_NEG 128
#define D_DIM 128
#define GAMMA 12.0f

// Output layout: for each part p in {0,1,2}:
//   pos  [S]      at p*PART_STRIDE
//   neg_t[S*K]    at p*PART_STRIDE + S
//   neg_h[S*K]    at p*PART_STRIDE + S + S*K
#define PART_STRIDE (S_NUM + 2 * S_NUM * K_NEG)   // 526336

__device__ __forceinline__ uint32_t smem_u32(const void* p) {
    uint32_t a;
    asm("{ .reg .u64 t; cvta.to.shared.u64 t, %1; cvt.u32.u64 %0, t; }"
        : "=r"(a) : "l"(p));
    return a;
}

__device__ __forceinline__ void cp_async16(uint32_t saddr, const void* gaddr) {
    asm volatile("cp.async.cg.shared.global [%0], [%1], 16;"
                 :: "r"(saddr), "l"(gaddr));
}

__device__ __forceinline__ void cp_commit() {
    asm volatile("cp.async.commit_group;");
}

template <int N>
__device__ __forceinline__ void cp_wait() {
    asm volatile("cp.async.wait_group %0;" :: "n"(N));
}

__device__ __forceinline__ void l2_prefetch(const void* gaddr) {
    asm volatile("prefetch.global.L2 [%0];" :: "l"(gaddr));
}

__global__ __launch_bounds__(128, 9)
void sample_score_kernel(
    const float* __restrict__ emb,        // [N, D]
    const float* __restrict__ relG2,      // [R2, D]
    const float* __restrict__ relTT,      // [R1, D]
    const float* __restrict__ relTO,      // [D]
    const int* __restrict__ h1, const int* __restrict__ r1, const int* __restrict__ t1,
    const int* __restrict__ nt1, const int* __restrict__ nh1,
    const int* __restrict__ h2, const int* __restrict__ r2, const int* __restrict__ t2,
    const int* __restrict__ nt2, const int* __restrict__ nh2,
    const int* __restrict__ h3, const int* __restrict__ t3,
    const int* __restrict__ nt3, const int* __restrict__ nh3,
    float* __restrict__ out)
{
    // Staging: [warp][slot][row][lane] 16B each -> 4*3*4*32*16 = 24 KB
    __shared__ float4 stage[4][3][4][32];

    const int s     = blockIdx.x >> 1;          // sample
    const int jbase = (blockIdx.x & 1) * 64;    // which half of the K=128 negatives
    const int part  = blockIdx.y;
    const int warp  = threadIdx.x >> 5;
    const int lane  = threadIdx.x & 31;

    // Select per-part pointers
    const int *hp, *tp, *ntp, *nhp;
    const int* rp;               // relation index array (nullptr for part 2)
    const float* rel;
    if (part == 0)      { hp=h1; rp=r1;      tp=t1; ntp=nt1; nhp=nh1; rel=relG2; }
    else if (part == 1) { hp=h2; rp=r2;      tp=t2; ntp=nt2; nhp=nh2; rel=relTT; }
    else                { hp=h3; rp=nullptr; tp=t3; ntp=nt3; nhp=nh3; rel=relTO; }

    const int j0 = jbase + warp * 16;    // this warp's 16 tail- and 16 head-negatives

    // Lane-parallel index load: lanes 0-15 carry nt indices, 16-31 carry nh indices.
    const int* nt_row = ntp + (size_t)s * K_NEG;
    const int* nh_row = nhp + (size_t)s * K_NEG;
    const int myidx = (lane < 16) ? __ldcs(nt_row + j0 + lane)
                                  : __ldcs(nh_row + j0 + (lane & 15));

    const unsigned FULL = 0xffffffffu;

    // smem base address for this lane's 16B chunk, row-stride = 512B, slot-stride = 2KB
    const uint32_t sbase = smem_u32(&stage[warp][0][0][lane]);

    // Issue a 4-row group (iteration i) into slot g. Rows:
    //   r0 = nt[2i], r1 = nt[2i+1], r2 = nh[2i], r3 = nh[2i+1]
    auto issue_group = [&](int i, int g) {
        const int a = __shfl_sync(FULL, myidx, 2 * i);
        const int b = __shfl_sync(FULL, myidx, 2 * i + 1);
        const int c = __shfl_sync(FULL, myidx, 16 + 2 * i);
        const int d = __shfl_sync(FULL, myidx, 17 + 2 * i);
        const uint32_t gb = sbase + g * 2048;
        cp_async16(gb,        emb + (size_t)a * D_DIM + lane * 4);
        cp_async16(gb + 512,  emb + (size_t)b * D_DIM + lane * 4);
        cp_async16(gb + 1024, emb + (size_t)c * D_DIM + lane * 4);
        cp_async16(gb + 1536, emb + (size_t)d * D_DIM + lane * 4);
        cp_commit();
    };

    // L2-prefetch a 4-row group: each lane touches the 128B line containing its
    // own 16B chunk; 32 lanes cover all 4 lines of each 512B row. No registers,
    // no smem, no cp.async slots -- pure DRAM->L2 demand brought forward.
    auto prefetch_group = [&](int i) {
        const int a = __shfl_sync(FULL, myidx, 2 * i);
        const int b = __shfl_sync(FULL, myidx, 2 * i + 1);
        const int c = __shfl_sync(FULL, myidx, 16 + 2 * i);
        const int d = __shfl_sync(FULL, myidx, 17 + 2 * i);
        l2_prefetch(emb + (size_t)a * D_DIM + lane * 4);
        l2_prefetch(emb + (size_t)b * D_DIM + lane * 4);
        l2_prefetch(emb + (size_t)c * D_DIM + lane * 4);
        l2_prefetch(emb + (size_t)d * D_DIM + lane * 4);
    };

    // ---- Prologue: fill the 3-slot ring, then L2-prefetch everything else ----
    issue_group(0, 0);
    issue_group(1, 1);
    issue_group(2, 2);
    prefetch_group(3);
    prefetch_group(4);
    prefetch_group(5);
    prefetch_group(6);
    prefetch_group(7);

    // ---- h, r, t gathers (overlap with the staged groups) ----
    const int hidx = __ldg(hp + s);
    const int tidx = __ldg(tp + s);
    const float4 hv = __ldg(reinterpret_cast<const float4*>(emb + (size_t)hidx * D_DIM) + lane);
    const float4 tv = __ldg(reinterpret_cast<const float4*>(emb + (size_t)tidx * D_DIM) + lane);
    float4 rv;
    if (rp) {
        const int ridx = __ldg(rp + s);
        rv = __ldg(reinterpret_cast<const float4*>(rel + (size_t)ridx * D_DIM) + lane);
    } else {
        rv = __ldg(reinterpret_cast<const float4*>(rel) + lane);
    }

    float4 hr, rmt;
    hr.x = hv.x + rv.x;  hr.y = hv.y + rv.y;  hr.z = hv.z + rv.z;  hr.w = hv.w + rv.w;
    rmt.x = rv.x - tv.x; rmt.y = rv.y - tv.y; rmt.z = rv.z - tv.z; rmt.w = rv.w - tv.w;

    float* out_pos = out + (size_t)part * PART_STRIDE;
    float* onT = out_pos + S_NUM + (size_t)s * K_NEG;
    float* onH = onT + (size_t)S_NUM * K_NEG;

    // ---- positive score (warp 0 of the jbase==0 block only) ----
    if (warp == 0 && jbase == 0) {
        float p = fabsf(hr.x - tv.x) + fabsf(hr.y - tv.y)
                + fabsf(hr.z - tv.z) + fabsf(hr.w - tv.w);
        #pragma unroll
        for (int o = 16; o > 0; o >>= 1)
            p += __shfl_xor_sync(FULL, p, o);
        if (lane == 0) out_pos[s] = GAMMA - p;
    }

    // ---- Main loop: 8 iterations, 3-deep ring of staged groups ----
    #pragma unroll
    for (int i = 0; i < 8; i++) {
        // Groups i .. min(i+2,7) are pending; need group i complete.
        if (i < 6)       cp_wait<2>();
        else if (i == 6) cp_wait<1>();
        else             cp_wait<0>();

        const int g = i % 3;
        // Each lane reads back exactly the 16B chunks it copied (no syncwarp needed).
        const float4 cta = stage[warp][g][0][lane];
        const float4 ctb = stage[warp][g][1][lane];
        const float4 cha = stage[warp][g][2][lane];
        const float4 chb = stage[warp][g][3][lane];

        // Early refill of the consumed slot: cp.async fill arrival is bounded
        // below by global latency (>> LDS retire), so issuing before the reduce
        // is safe. Rows were L2-prefetched in the prologue -> mostly L2 hits.
        if (i < 5) issue_group(i + 3, g);

        float sa = fabsf(hr.x - cta.x) + fabsf(hr.y - cta.y)
                 + fabsf(hr.z - cta.z) + fabsf(hr.w - cta.w);
        float sb = fabsf(hr.x - ctb.x) + fabsf(hr.y - ctb.y)
                 + fabsf(hr.z - ctb.z) + fabsf(hr.w - ctb.w);
        float sc = fabsf(cha.x + rmt.x) + fabsf(cha.y + rmt.y)
                 + fabsf(cha.z + rmt.z) + fabsf(cha.w + rmt.w);
        float sd = fabsf(chb.x + rmt.x) + fabsf(chb.y + rmt.y)
                 + fabsf(chb.z + rmt.z) + fabsf(chb.w + rmt.w);

        // 9-shuffle 4-value warp reduction:
        // after this, lane0=sa_tot, lane8=sc_tot, lane16=sb_tot, lane24=sd_tot
        sa += __shfl_xor_sync(FULL, sa, 16);
        sb += __shfl_xor_sync(FULL, sb, 16);
        sc += __shfl_xor_sync(FULL, sc, 16);
        sd += __shfl_xor_sync(FULL, sd, 16);
        float mab = (lane & 16) ? sb : sa;
        float mcd = (lane & 16) ? sd : sc;
        mab += __shfl_xor_sync(FULL, mab, 8);
        mcd += __shfl_xor_sync(FULL, mcd, 8);
        float m = (lane & 8) ? mcd : mab;
        m += __shfl_xor_sync(FULL, m, 4);
        m += __shfl_xor_sync(FULL, m, 2);
        m += __shfl_xor_sync(FULL, m, 1);

        const int j = j0 + 2 * i;
        const float val = GAMMA - m;
        if (lane == 0)       __stcs(onT + j,     val);
        else if (lane == 8)  __stcs(onH + j,     val);
        else if (lane == 16) __stcs(onT + j + 1, val);
        else if (lane == 24) __stcs(onH + j + 1, val);
    }
}

extern "C" void kernel_launch(void* const* d_in, const int* in_sizes, int n_in,
                              void* d_out, int out_size) {
    const float* emb   = (const float*)d_in[0];
    const float* relG2 = (const float*)d_in[1];
    const float* relTT = (const float*)d_in[2];
    const float* relTO = (const float*)d_in[3];
    const int* h1  = (const int*)d_in[4];
    const int* r1  = (const int*)d_in[5];
    const int* t1  = (const int*)d_in[6];
    const int* nt1 = (const int*)d_in[7];
    const int* nh1 = (const int*)d_in[8];
    const int* h2  = (const int*)d_in[9];
    const int* r2  = (const int*)d_in[10];
    const int* t2  = (const int*)d_in[11];
    const int* nt2 = (const int*)d_in[12];
    const int* nh2 = (const int*)d_in[13];
    const int* h3  = (const int*)d_in[14];
    const int* t3  = (const int*)d_in[15];
    const int* nt3 = (const int*)d_in[16];
    const int* nh3 = (const int*)d_in[17];

    dim3 grid(2 * S_NUM, 3);
    sample_score_kernel<<<grid, 128>>>(
        emb, relG2, relTT, relTO,
        h1, r1, t1, nt1, nh1,
        h2, r2, t2, nt2, nh2,
        h3, t3, nt3, nh3,
        (float*)d_out);
}

// round 17
// speedup vs baseline: 1.0397x; 1.0397x over previous
#include <cuda_runtime.h>
#include <cstdint>

// Problem constants (match reference)
#define S_NUM 2048
#define K_NEG 128
#define D_DIM 128
#define GAMMA 12.0f

// Output layout: for each part p in {0,1,2}:
//   pos  [S]      at p*PART_STRIDE
//   neg_t[S*K]    at p*PART_STRIDE + S
//   neg_h[S*K]    at p*PART_STRIDE + S + S*K
#define PART_STRIDE (S_NUM + 2 * S_NUM * K_NEG)   // 526336

__device__ __forceinline__ uint32_t smem_u32(const void* p) {
    uint32_t a;
    asm("{ .reg .u64 t; cvta.to.shared.u64 t, %1; cvt.u32.u64 %0, t; }"
        : "=r"(a) : "l"(p));
    return a;
}

__device__ __forceinline__ void cp_async16(uint32_t saddr, const void* gaddr) {
    asm volatile("cp.async.cg.shared.global [%0], [%1], 16;"
                 :: "r"(saddr), "l"(gaddr));
}

__device__ __forceinline__ void cp_commit() {
    asm volatile("cp.async.commit_group;");
}

template <int N>
__device__ __forceinline__ void cp_wait() {
    asm volatile("cp.async.wait_group %0;" :: "n"(N));
}

__global__ __launch_bounds__(128, 9)
void sample_score_kernel(
    const float* __restrict__ emb,        // [N, D]
    const float* __restrict__ relG2,      // [R2, D]
    const float* __restrict__ relTT,      // [R1, D]
    const float* __restrict__ relTO,      // [D]
    const int* __restrict__ h1, const int* __restrict__ r1, const int* __restrict__ t1,
    const int* __restrict__ nt1, const int* __restrict__ nh1,
    const int* __restrict__ h2, const int* __restrict__ r2, const int* __restrict__ t2,
    const int* __restrict__ nt2, const int* __restrict__ nh2,
    const int* __restrict__ h3, const int* __restrict__ t3,
    const int* __restrict__ nt3, const int* __restrict__ nh3,
    float* __restrict__ out)
{
    // Staging: [warp][slot][row][lane] 16B each -> 4*3*4*32*16 = 24 KB
    __shared__ float4 stage[4][3][4][32];

    const int s     = blockIdx.x >> 1;          // sample
    const int jbase = (blockIdx.x & 1) * 64;    // which half of the K=128 negatives
    const int part  = blockIdx.y;
    const int warp  = threadIdx.x >> 5;
    const int lane  = threadIdx.x & 31;

    // Select per-part pointers
    const int *hp, *tp, *ntp, *nhp;
    const int* rp;               // relation index array (nullptr for part 2)
    const float* rel;
    if (part == 0)      { hp=h1; rp=r1;      tp=t1; ntp=nt1; nhp=nh1; rel=relG2; }
    else if (part == 1) { hp=h2; rp=r2;      tp=t2; ntp=nt2; nhp=nh2; rel=relTT; }
    else                { hp=h3; rp=nullptr; tp=t3; ntp=nt3; nhp=nh3; rel=relTO; }

    const int j0 = jbase + warp * 16;    // this warp's 16 tail- and 16 head-negatives

    // Lane-parallel index load: lanes 0-15 carry nt indices, 16-31 carry nh indices.
    const int* nt_row = ntp + (size_t)s * K_NEG;
    const int* nh_row = nhp + (size_t)s * K_NEG;
    const int myidx = (lane < 16) ? __ldcs(nt_row + j0 + lane)
                                  : __ldcs(nh_row + j0 + (lane & 15));

    const unsigned FULL = 0xffffffffu;

    // smem base address for this lane's 16B chunk, row-stride = 512B, slot-stride = 2KB
    const uint32_t sbase = smem_u32(&stage[warp][0][0][lane]);

    // Issue a 4-row group (iteration i) into slot g. Rows:
    //   r0 = nt[2i], r1 = nt[2i+1], r2 = nh[2i], r3 = nh[2i+1]
    auto issue_group = [&](int i, int g) {
        const int a = __shfl_sync(FULL, myidx, 2 * i);
        const int b = __shfl_sync(FULL, myidx, 2 * i + 1);
        const int c = __shfl_sync(FULL, myidx, 16 + 2 * i);
        const int d = __shfl_sync(FULL, myidx, 17 + 2 * i);
        const uint32_t gb = sbase + g * 2048;
        cp_async16(gb,        emb + (size_t)a * D_DIM + lane * 4);
        cp_async16(gb + 512,  emb + (size_t)b * D_DIM + lane * 4);
        cp_async16(gb + 1024, emb + (size_t)c * D_DIM + lane * 4);
        cp_async16(gb + 1536, emb + (size_t)d * D_DIM + lane * 4);
        cp_commit();
    };

    // ---- Prologue: fill the 3-slot ring before anything else ----
    issue_group(0, 0);
    issue_group(1, 1);
    issue_group(2, 2);

    // ---- h, r, t gathers (overlap with the staged groups) ----
    const int hidx = __ldg(hp + s);
    const int tidx = __ldg(tp + s);
    const float4 hv = __ldg(reinterpret_cast<const float4*>(emb + (size_t)hidx * D_DIM) + lane);
    const float4 tv = __ldg(reinterpret_cast<const float4*>(emb + (size_t)tidx * D_DIM) + lane);
    float4 rv;
    if (rp) {
        const int ridx = __ldg(rp + s);
        rv = __ldg(reinterpret_cast<const float4*>(rel + (size_t)ridx * D_DIM) + lane);
    } else {
        rv = __ldg(reinterpret_cast<const float4*>(rel) + lane);
    }

    float4 hr, rmt;
    hr.x = hv.x + rv.x;  hr.y = hv.y + rv.y;  hr.z = hv.z + rv.z;  hr.w = hv.w + rv.w;
    rmt.x = rv.x - tv.x; rmt.y = rv.y - tv.y; rmt.z = rv.z - tv.z; rmt.w = rv.w - tv.w;

    float* out_pos = out + (size_t)part * PART_STRIDE;
    float* onT = out_pos + S_NUM + (size_t)s * K_NEG;
    float* onH = onT + (size_t)S_NUM * K_NEG;

    // ---- positive score (warp 0 of the jbase==0 block only) ----
    if (warp == 0 && jbase == 0) {
        float p = fabsf(hr.x - tv.x) + fabsf(hr.y - tv.y)
                + fabsf(hr.z - tv.z) + fabsf(hr.w - tv.w);
        #pragma unroll
        for (int o = 16; o > 0; o >>= 1)
            p += __shfl_xor_sync(FULL, p, o);
        if (lane == 0) out_pos[s] = GAMMA - p;
    }

    // ---- Main loop: 8 iterations, 3-deep ring of staged groups ----
    #pragma unroll
    for (int i = 0; i < 8; i++) {
        // Groups i .. min(i+2,7) are pending; need group i complete.
        if (i < 6)       cp_wait<2>();
        else if (i == 6) cp_wait<1>();
        else             cp_wait<0>();

        const int g = i % 3;
        // Each lane reads back exactly the 16B chunks it copied (no syncwarp needed).
        const float4 cta = stage[warp][g][0][lane];
        const float4 ctb = stage[warp][g][1][lane];
        const float4 cha = stage[warp][g][2][lane];
        const float4 chb = stage[warp][g][3][lane];

        // Early refill of the consumed slot: cp.async fill arrival is bounded
        // below by global latency (>> LDS retire), so issuing before the reduce
        // is safe and keeps 12 rows in flight per warp.
        if (i < 5) issue_group(i + 3, g);

        float sa = fabsf(hr.x - cta.x) + fabsf(hr.y - cta.y)
                 + fabsf(hr.z - cta.z) + fabsf(hr.w - cta.w);
        float sb = fabsf(hr.x - ctb.x) + fabsf(hr.y - ctb.y)
                 + fabsf(hr.z - ctb.z) + fabsf(hr.w - ctb.w);
        float sc = fabsf(cha.x + rmt.x) + fabsf(cha.y + rmt.y)
                 + fabsf(cha.z + rmt.z) + fabsf(cha.w + rmt.w);
        float sd = fabsf(chb.x + rmt.x) + fabsf(chb.y + rmt.y)
                 + fabsf(chb.z + rmt.z) + fabsf(chb.w + rmt.w);

        // 9-shuffle 4-value warp reduction:
        // after this, lane0=sa_tot, lane8=sc_tot, lane16=sb_tot, lane24=sd_tot
        sa += __shfl_xor_sync(FULL, sa, 16);
        sb += __shfl_xor_sync(FULL, sb, 16);
        sc += __shfl_xor_sync(FULL, sc, 16);
        sd += __shfl_xor_sync(FULL, sd, 16);
        float mab = (lane & 16) ? sb : sa;
        float mcd = (lane & 16) ? sd : sc;
        mab += __shfl_xor_sync(FULL, mab, 8);
        mcd += __shfl_xor_sync(FULL, mcd, 8);
        float m = (lane & 8) ? mcd : mab;
        m += __shfl_xor_sync(FULL, m, 4);
        m += __shfl_xor_sync(FULL, m, 2);
        m += __shfl_xor_sync(FULL, m, 1);

        const int j = j0 + 2 * i;
        const float val = GAMMA - m;
        if (lane == 0)       __stcs(onT + j,     val);
        else if (lane == 8)  __stcs(onH + j,     val);
        else if (lane == 16) __stcs(onT + j + 1, val);
        else if (lane == 24) __stcs(onH + j + 1, val);
    }
}

extern "C" void kernel_launch(void* const* d_in, const int* in_sizes, int n_in,
                              void* d_out, int out_size) {
    const float* emb   = (const float*)d_in[0];
    const float* relG2 = (const float*)d_in[1];
    const float* relTT = (const float*)d_in[2];
    const float* relTO = (const float*)d_in[3];
    const int* h1  = (const int*)d_in[4];
    const int* r1  = (const int*)d_in[5];
    const int* t1  = (const int*)d_in[6];
    const int* nt1 = (const int*)d_in[7];
    const int* nh1 = (const int*)d_in[8];
    const int* h2  = (const int*)d_in[9];
    const int* r2  = (const int*)d_in[10];
    const int* t2  = (const int*)d_in[11];
    const int* nt2 = (const int*)d_in[12];
    const int* nh2 = (const int*)d_in[13];
    const int* h3  = (const int*)d_in[14];
    const int* t3  = (const int*)d_in[15];
    const int* nt3 = (const int*)d_in[16];
    const int* nh3 = (const int*)d_in[17];

    dim3 grid(2 * S_NUM, 3);
    sample_score_kernel<<<grid, 128>>>(
        emb, relG2, relTT, relTO,
        h1, r1, t1, nt1, nh1,
        h2, r2, t2, nt2, nh2,
        h3, t3, nt3, nh3,
        (float*)d_out);
}